// round 16
// baseline (speedup 1.0000x reference)
#include <cuda_runtime.h>
#include <math.h>

// Problem constants
#define BN   8192
#define DN   64
#define CTXN 256
#define HN   512
#define ROWS 16        // rows per CTA (2 per warp)
#define NTHR 256
#define CTXP 20        // padded row-stride for staged context (80B, 16B-aligned)
#define PRIV 1032      // per-warp private a1 stride in floats (512*2 + 8 pad)
#define EPSOFF (8 * PRIV)   // float offset of eps staging area
#define EPSP 17             // padded eps stride

typedef unsigned long long u64;

// ---------------- static device scratch (no allocations allowed) -------------
__device__ __align__(16) float g_W2r[HN * HN];      // [k_in][n_out], permuted+masked
__device__ __align__(16) float g_W1r[DN * HN];      // [input d][p], permuted+masked
__device__ __align__(16) float g_WomP[DN * 2 * HN]; // [step i][unit p][mu_w, sc_w]
__device__ __align__(16) float g_Wcr[CTXN * HN];    // [c][p] permuted Wc
__device__ __align__(16) float g_b1r[HN];
__device__ __align__(16) float g_b2r[HN];

// ------------- degree-sorted permutation (analytic) --------------------------
// mh[h] = h % 63 + 1 ; degrees 1..8 appear 9x, 9..63 appear 8x.
__device__ __forceinline__ int degp(int p) { return (p < 72) ? (p / 9 + 1) : (p / 8); }
__device__ __forceinline__ int origp(int p) {
    int d, j;
    if (p < 72) { d = p / 9 + 1; j = p - 9 * (d - 1); }
    else        { d = p / 8;     j = p - 8 * d; }
    return (d - 1) + 63 * j;
}
__device__ __forceinline__ int cntd(int d) {
    return (d <= 0) ? 0 : ((d <= 8) ? 9 * d : 8 * d + 8);
}

// ------------- packed f32x2 helpers ------------------------------------------
__device__ __forceinline__ u64 dup2(float a) {
    u64 r; asm("mov.b64 %0, {%1, %1};" : "=l"(r) : "f"(a)); return r;
}
__device__ __forceinline__ u64 pk2(float a, float b) {
    u64 r; asm("mov.b64 %0, {%1, %2};" : "=l"(r) : "f"(a), "f"(b)); return r;
}
__device__ __forceinline__ void fma2(u64& d, u64 a, u64 b) {
    asm("fma.rn.f32x2 %0, %1, %2, %0;" : "+l"(d) : "l"(a), "l"(b));
}
__device__ __forceinline__ void add2(u64& d, u64 a) {
    asm("add.rn.f32x2 %0, %0, %1;" : "+l"(d) : "l"(a));
}
__device__ __forceinline__ void unpk(u64 v, float& a, float& b) {
    asm("mov.b64 {%0, %1}, %2;" : "=f"(a), "=f"(b) : "l"(v));
}

// ------------- weight preparation (masked, permuted) --------------------------
__global__ void prep_kernel(const float* __restrict__ W1, const float* __restrict__ b1,
                            const float* __restrict__ Wc, const float* __restrict__ W2,
                            const float* __restrict__ b2, const float* __restrict__ Wo) {
    int idx = blockIdx.x * blockDim.x + threadIdx.x;
    if (idx < HN * HN) {
        int k = idx / HN, n = idx % HN;
        int dn = degp(n), dk = degp(k);
        g_W2r[idx] = (dn >= dk) ? W2[origp(n) * HN + origp(k)] : 0.f;
    }
    if (idx < DN * HN) {
        int i = idx / HN, p = idx % HN;
        int dp = degp(p), op = origp(p);
        g_W1r[idx] = (dp >= i + 1) ? W1[op * DN + i] : 0.f;
        bool m = (dp <= i);
        g_WomP[i * (2 * HN) + 2 * p]     = m ? Wo[i * HN + op] : 0.f;
        g_WomP[i * (2 * HN) + 2 * p + 1] = m ? Wo[(DN + i) * HN + op] : 0.f;
    }
    if (idx < CTXN * HN) {
        int c = idx / HN, p = idx % HN;
        g_Wcr[idx] = Wc[origp(p) * CTXN + c];
    }
    if (idx < HN) {
        int op = origp(idx);
        g_b1r[idx] = b1[op];
        g_b2r[idx] = b2[op];
    }
}

// one k-row of weights for this lane's 16 units (interleaved: j*128 + lane*4)
struct W16 { ulonglong2 q0, q1, q2, q3; };
__device__ __forceinline__ void loadW16(W16& g, const float* p) {
    g.q0 = *(const ulonglong2*)(p);
    g.q1 = *(const ulonglong2*)(p + 128);
    g.q2 = *(const ulonglong2*)(p + 256);
    g.q3 = *(const ulonglong2*)(p + 384);
}

// ------------- main persistent kernel ----------------------------------------
// Warp-autonomous incremental MADE, 2 rows per warp for high occupancy.
// Warp w owns batch rows {2w, 2w+1} and ALL 512 units. Lane owns 16 units
// (4 float4 quads at j*128+lane*4) x 2 rows: S = 16 u64 = 32 regs.
// No __syncthreads in the recurrence; in-warp shfl reductions only.
__global__ void __launch_bounds__(NTHR, 3)
made_kernel(const float* __restrict__ ctx, const float* __restrict__ eps,
            const float* __restrict__ bo, float* __restrict__ out) {
    extern __shared__ float smem[];
    const int t    = threadIdx.x;
    const int wid  = t >> 5;
    const int lane = t & 31;
    const int row0 = blockIdx.x * ROWS;
    float* a1w = smem + wid * PRIV;        // this warp's private a1 [512][2]

    // ---- Phase 0: stage context transposed (stride CTXP) + eps [i][r] ----
    for (int idx = t; idx < CTXN * ROWS; idx += NTHR) {
        int r = idx >> 8;                  // 0..15
        int c = idx & 255;
        smem[c * CTXP + r] = ctx[(row0 + r) * CTXN + c];
    }
    for (int idx = t; idx < ROWS * DN; idx += NTHR) {
        int r = idx >> 6;
        int i = idx & 63;
        smem[EPSOFF + i * EPSP + r] = eps[(row0 + r) * DN + i];
    }
    __syncthreads();

    // ---- Phase 1: ctx GEMM (warp = 64 units x 16 rows) ----
    {
        const int rg  = lane >> 3;          // 4 row groups of 4
        const int ull = lane & 7;           // 8 units
        const int nb1 = wid * 64 + ull * 8;
        const int r0t = rg * 4;
        u64 acc1[4][4];
#pragma unroll
        for (int a = 0; a < 4; a++)
#pragma unroll
            for (int b = 0; b < 4; b++) acc1[a][b] = 0ull;
        const float* wp = g_Wcr + nb1;
        const float* hp = smem + r0t;
#pragma unroll 2
        for (int c = 0; c < CTXN; c++) {
            ulonglong2 wA = *(const ulonglong2*)(wp);
            ulonglong2 wB = *(const ulonglong2*)(wp + 4);
            wp += HN;
            float4 v = *(const float4*)(hp);
            hp += CTXP;
            u64 h[4];
            h[0] = dup2(v.x); h[1] = dup2(v.y); h[2] = dup2(v.z); h[3] = dup2(v.w);
#pragma unroll
            for (int r = 0; r < 4; r++) {
                fma2(acc1[0][r], wA.x, h[r]);
                fma2(acc1[1][r], wA.y, h[r]);
                fma2(acc1[2][r], wB.x, h[r]);
                fma2(acc1[3][r], wB.y, h[r]);
            }
        }
        __syncthreads();   // everyone done reading staged ctx
        // scatter (+b1) into per-warp private a1 [p][2]
#pragma unroll
        for (int up = 0; up < 4; up++) {
            int n0 = nb1 + 2 * up;
            float bA = g_b1r[n0], bB = g_b1r[n0 + 1];
#pragma unroll
            for (int rr = 0; rr < 4; rr++) {
                float lo, hi; unpk(acc1[up][rr], lo, hi);
                int r = r0t + rr;
                float* dst = smem + (r >> 1) * PRIV + (r & 1);
                dst[n0 * 2]       = lo + bA;
                dst[(n0 + 1) * 2] = hi + bB;
            }
        }
    }
    __syncthreads();   // a1 arrays complete; phase 2 is barrier-free

    // ---- Phase 2: D sequential steps, warp-autonomous ----
    // S[2j+c][r]: unit pair (j*128 + lane*4 + 2c, +1), row r in {0,1}. Init b2.
    u64 S[8][2];
#pragma unroll
    for (int j = 0; j < 4; j++) {
        float4 b2v = *(const float4*)(g_b2r + j * 128 + lane * 4);
        S[2 * j][0]     = pk2(b2v.x, b2v.y);
        S[2 * j][1]     = S[2 * j][0];
        S[2 * j + 1][0] = pk2(b2v.z, b2v.w);
        S[2 * j + 1][1] = S[2 * j + 1][0];
    }

    const float* wlane = g_W2r + lane * 4;   // + k*HN + j*128
    W16 pf;
    loadW16(pf, wlane);                       // prefetch k = 0

    int kprev = 0;
    for (int i = 0; i < DN; i++) {
        const int ncur = cntd(i);

        // -- S update with newly frozen rows [kprev, ncur) --
#pragma unroll 1
        for (int k = kprev; k < ncur; k++) {
            W16 cw = pf;                              // rename, no MOVs
            int kn = (k + 1 < HN) ? (k + 1) : (HN - 1);
            loadW16(pf, wlane + kn * HN);             // distance-1 register prefetch
            float2 av = *(const float2*)(a1w + k * 2);   // relu'd, warp-broadcast
            u64 h0 = dup2(av.x), h1 = dup2(av.y);
            fma2(S[0][0], cw.q0.x, h0); fma2(S[0][1], cw.q0.x, h1);
            fma2(S[1][0], cw.q0.y, h0); fma2(S[1][1], cw.q0.y, h1);
            fma2(S[2][0], cw.q1.x, h0); fma2(S[2][1], cw.q1.x, h1);
            fma2(S[3][0], cw.q1.y, h0); fma2(S[3][1], cw.q1.y, h1);
            fma2(S[4][0], cw.q2.x, h0); fma2(S[4][1], cw.q2.x, h1);
            fma2(S[5][0], cw.q2.y, h0); fma2(S[5][1], cw.q2.y, h1);
            fma2(S[6][0], cw.q3.x, h0); fma2(S[6][1], cw.q3.x, h1);
            fma2(S[7][0], cw.q3.y, h0); fma2(S[7][1], cw.q3.y, h1);
        }
        kprev = ncur;

        // -- epilogue: P[r] += dup2(relu(S_n)) * (wm_n, ws_n), active quads only --
        u64 P[2] = {0ull, 0ull};
        const float* wpp = g_WomP + i * (2 * HN) + lane * 8;
#pragma unroll
        for (int j = 0; j < 4; j++) {
            if (j * 128 < ncur) {                    // warp-uniform quad skip
                ulonglong2 wa = *(const ulonglong2*)(wpp + j * 256);
                ulonglong2 wb = *(const ulonglong2*)(wpp + j * 256 + 4);
                float s0, s1, u0, u1;
                unpk(S[2 * j][0], s0, s1);
                unpk(S[2 * j][1], u0, u1);
                fma2(P[0], dup2(fmaxf(s0, 0.f)), wa.x);
                fma2(P[1], dup2(fmaxf(u0, 0.f)), wa.x);
                fma2(P[0], dup2(fmaxf(s1, 0.f)), wa.y);
                fma2(P[1], dup2(fmaxf(u1, 0.f)), wa.y);
                unpk(S[2 * j + 1][0], s0, s1);
                unpk(S[2 * j + 1][1], u0, u1);
                fma2(P[0], dup2(fmaxf(s0, 0.f)), wb.x);
                fma2(P[1], dup2(fmaxf(u0, 0.f)), wb.x);
                fma2(P[0], dup2(fmaxf(s1, 0.f)), wb.y);
                fma2(P[1], dup2(fmaxf(u1, 0.f)), wb.y);
            }
        }

        // u64 butterfly: all lanes end with full (mu, sc) per row
#pragma unroll
        for (int off = 16; off > 0; off >>= 1) {
            u64 o0 = __shfl_xor_sync(0xffffffffu, P[0], off);
            u64 o1 = __shfl_xor_sync(0xffffffffu, P[1], off);
            add2(P[0], o0);
            add2(P[1], o1);
        }

        // -- lane-split z: lane computes row (lane&1), fast softplus --
        const int rw = lane & 1;
        float muS, scS; unpk(P[rw], muS, scS);
        float m  = muS + __ldg(bo + i);
        float ps = scS + __ldg(bo + DN + i);
        float scl = fmaxf(ps, 0.f) + __logf(1.f + __expf(-fabsf(ps)));
        float ev  = smem[EPSOFF + i * EPSP + wid * 2 + rw];
        float zz  = m + scl * ev;
        if (lane < 2) {
            int g = (row0 + wid * 2 + lane) * DN + i;
            out[g]               = zz;
            out[BN * DN + g]     = m;
            out[2 * BN * DN + g] = scl;
        }
        float z0 = __shfl_sync(0xffffffffu, zz, 0);
        float z1 = __shfl_sync(0xffffffffu, zz, 1);

        // -- rank-1 a1 update on suffix [ncur, HN); freeze-relu [ncur, nfreeze) --
        if (i < DN - 1) {
            const int nfreeze = cntd(i + 1);
            const float* w1 = g_W1r + i * HN;
            for (int p = ncur + lane; p < HN; p += 32) {
                float w = w1[p];
                float2 a = *(float2*)(a1w + p * 2);
                a.x = fmaf(z0, w, a.x);
                a.y = fmaf(z1, w, a.y);
                if (p < nfreeze) {          // freezes now: apply relu permanently
                    a.x = fmaxf(a.x, 0.f);
                    a.y = fmaxf(a.y, 0.f);
                }
                *(float2*)(a1w + p * 2) = a;
            }
        }
        __syncwarp();   // converge; order rank-1 STS before next step's LDS
    }
}

// ------------- launch ---------------------------------------------------------
extern "C" void kernel_launch(void* const* d_in, const int* in_sizes, int n_in,
                              void* d_out, int out_size) {
    (void)in_sizes; (void)n_in; (void)out_size;
    const float* ctx = (const float*)d_in[0];
    const float* eps = (const float*)d_in[1];
    const float* W1  = (const float*)d_in[2];
    const float* b1  = (const float*)d_in[3];
    const float* Wc  = (const float*)d_in[4];
    const float* W2  = (const float*)d_in[5];
    const float* b2  = (const float*)d_in[6];
    const float* Wo  = (const float*)d_in[7];
    const float* bo  = (const float*)d_in[8];
    float* out = (float*)d_out;

    prep_kernel<<<(HN * HN + 255) / 256, 256>>>(W1, b1, Wc, W2, b2, Wo);

    // smem: 8 warps x PRIV + eps staging [64][17]  (ctx staging overlays a1)
    const int smem_bytes = (8 * PRIV + DN * EPSP) * (int)sizeof(float);   // 37376 B
    cudaFuncSetAttribute(made_kernel, cudaFuncAttributeMaxDynamicSharedMemorySize, smem_bytes);
    made_kernel<<<BN / ROWS, NTHR, smem_bytes>>>(ctx, eps, bo, out);
}

// round 17
// speedup vs baseline: 2.0403x; 2.0403x over previous
#include <cuda_runtime.h>
#include <math.h>

// Problem constants
#define BN   8192
#define DN   64
#define CTXN 256
#define HN   512
#define ROWS 32        // rows per CTA (4 per warp)
#define NTHR 256
#define CTXP 36        // padded row-stride for staged context (16B-aligned)
#define PRIV 2048      // per-warp private a1 stride in floats (512*4)
#define WOFF (8 * PRIV)        // float offset of weight ring
#define WSTRIDE (9 * HN)       // one ring buffer: 9 rows x 512
#define EPSOFF (WOFF + 2 * WSTRIDE)   // eps staging
#define EPSP 33

typedef unsigned long long u64;

// ---------------- static device scratch (no allocations allowed) -------------
__device__ __align__(16) float g_W2r[HN * HN];      // [k_in][n_out], permuted+masked
__device__ __align__(16) float g_W1r[DN * HN];      // [input d][p], permuted+masked
__device__ __align__(16) float g_WomP[DN * 2 * HN]; // [step i][unit p][mu_w, sc_w]
__device__ __align__(16) float g_Wcr[CTXN * HN];    // [c][p] permuted Wc
__device__ __align__(16) float g_b1r[HN];
__device__ __align__(16) float g_b2r[HN];

// ------------- degree-sorted permutation (analytic) --------------------------
// mh[h] = h % 63 + 1 ; degrees 1..8 appear 9x, 9..63 appear 8x.
__device__ __forceinline__ int degp(int p) { return (p < 72) ? (p / 9 + 1) : (p / 8); }
__device__ __forceinline__ int origp(int p) {
    int d, j;
    if (p < 72) { d = p / 9 + 1; j = p - 9 * (d - 1); }
    else        { d = p / 8;     j = p - 8 * d; }
    return (d - 1) + 63 * j;
}
__device__ __forceinline__ int cntd(int d) {
    return (d <= 0) ? 0 : ((d <= 8) ? 9 * d : 8 * d + 8);
}

// ------------- packed f32x2 + async helpers -----------------------------------
__device__ __forceinline__ u64 dup2(float a) {
    u64 r; asm("mov.b64 %0, {%1, %1};" : "=l"(r) : "f"(a)); return r;
}
__device__ __forceinline__ u64 pk2(float a, float b) {
    u64 r; asm("mov.b64 %0, {%1, %2};" : "=l"(r) : "f"(a), "f"(b)); return r;
}
__device__ __forceinline__ void fma2(u64& d, u64 a, u64 b) {
    asm("fma.rn.f32x2 %0, %1, %2, %0;" : "+l"(d) : "l"(a), "l"(b));
}
__device__ __forceinline__ void add2(u64& d, u64 a) {
    asm("add.rn.f32x2 %0, %0, %1;" : "+l"(d) : "l"(a));
}
__device__ __forceinline__ void unpk(u64 v, float& a, float& b) {
    asm("mov.b64 {%0, %1}, %2;" : "=f"(a), "=f"(b) : "l"(v));
}
__device__ __forceinline__ unsigned smem_u32(const void* p) {
    unsigned a;
    asm("{ .reg .u64 t; cvta.to.shared.u64 t, %1; cvt.u32.u64 %0, t; }"
        : "=r"(a) : "l"(p));
    return a;
}
__device__ __forceinline__ void cpa16(unsigned s, const void* g) {
    asm volatile("cp.async.cg.shared.global [%0], [%1], 16;" :: "r"(s), "l"(g));
}
#define CP_COMMIT() asm volatile("cp.async.commit_group;" ::: "memory")
#define CP_WAIT0()  asm volatile("cp.async.wait_group 0;"  ::: "memory")

// ------------- weight preparation (masked, permuted) --------------------------
__global__ void prep_kernel(const float* __restrict__ W1, const float* __restrict__ b1,
                            const float* __restrict__ Wc, const float* __restrict__ W2,
                            const float* __restrict__ b2, const float* __restrict__ Wo) {
    int idx = blockIdx.x * blockDim.x + threadIdx.x;
    if (idx < HN * HN) {
        int k = idx / HN, n = idx % HN;
        int dn = degp(n), dk = degp(k);
        g_W2r[idx] = (dn >= dk) ? W2[origp(n) * HN + origp(k)] : 0.f;
    }
    if (idx < DN * HN) {
        int i = idx / HN, p = idx % HN;
        int dp = degp(p), op = origp(p);
        g_W1r[idx] = (dp >= i + 1) ? W1[op * DN + i] : 0.f;
        bool m = (dp <= i);
        g_WomP[i * (2 * HN) + 2 * p]     = m ? Wo[i * HN + op] : 0.f;
        g_WomP[i * (2 * HN) + 2 * p + 1] = m ? Wo[(DN + i) * HN + op] : 0.f;
    }
    if (idx < CTXN * HN) {
        int c = idx / HN, p = idx % HN;
        g_Wcr[idx] = Wc[origp(p) * CTXN + c];
    }
    if (idx < HN) {
        int op = origp(idx);
        g_b1r[idx] = b1[op];
        g_b2r[idx] = b2[op];
    }
}

// ------------- main persistent kernel ----------------------------------------
// Warp = 4 rows x 512 units (S = 32 u64 regs). Incremental S; each of 512
// weight rows is staged ONCE per CTA into a cp.async double-buffered smem
// ring and consumed by all 8 warps via LDS (no L2 latency in the hot loop).
// One __syncthreads per step.
__global__ void __launch_bounds__(NTHR, 2)
made_kernel(const float* __restrict__ ctx, const float* __restrict__ eps,
            const float* __restrict__ bo, float* __restrict__ out) {
    extern __shared__ float smem[];
    const int t    = threadIdx.x;
    const int wid  = t >> 5;
    const int lane = t & 31;
    const int row0 = blockIdx.x * ROWS;
    float* a1w = smem + wid * PRIV;        // this warp's private a1 [512][4]
    const unsigned smem_base = smem_u32(smem);

    // ---- Phase 0: stage context transposed (stride CTXP) + eps [i][r] ----
    for (int idx = t; idx < CTXN * ROWS; idx += NTHR) {
        int r = idx >> 8;
        int c = idx & 255;
        smem[c * CTXP + r] = ctx[(row0 + r) * CTXN + c];
    }
    for (int idx = t; idx < ROWS * DN; idx += NTHR) {
        int r = idx >> 6;
        int i = idx & 63;
        smem[EPSOFF + i * EPSP + r] = eps[(row0 + r) * DN + i];
    }
    __syncthreads();

    // ---- Phase 1: ctx GEMM (warp = 64 units x 32 rows) ----
    {
        const int rg  = lane >> 3;
        const int ull = lane & 7;
        const int nb1 = wid * 64 + ull * 8;
        const int r0t = rg * 8;
        u64 acc1[4][8];
#pragma unroll
        for (int a = 0; a < 4; a++)
#pragma unroll
            for (int b = 0; b < 8; b++) acc1[a][b] = 0ull;
        const float* wp = g_Wcr + nb1;
        const float* hp = smem + r0t;
#pragma unroll 2
        for (int c = 0; c < CTXN; c++) {
            ulonglong2 wA = *(const ulonglong2*)(wp);
            ulonglong2 wB = *(const ulonglong2*)(wp + 4);
            wp += HN;
            float4 v0 = *(const float4*)(hp);
            float4 v1 = *(const float4*)(hp + 4);
            hp += CTXP;
            u64 h[8];
            h[0] = dup2(v0.x); h[1] = dup2(v0.y); h[2] = dup2(v0.z); h[3] = dup2(v0.w);
            h[4] = dup2(v1.x); h[5] = dup2(v1.y); h[6] = dup2(v1.z); h[7] = dup2(v1.w);
#pragma unroll
            for (int r = 0; r < 8; r++) {
                fma2(acc1[0][r], wA.x, h[r]);
                fma2(acc1[1][r], wA.y, h[r]);
                fma2(acc1[2][r], wB.x, h[r]);
                fma2(acc1[3][r], wB.y, h[r]);
            }
        }
        __syncthreads();   // everyone done reading staged ctx
#pragma unroll
        for (int up = 0; up < 4; up++) {
            int n0 = nb1 + 2 * up;
            float bA = g_b1r[n0], bB = g_b1r[n0 + 1];
#pragma unroll
            for (int rr = 0; rr < 8; rr++) {
                float lo, hi; unpk(acc1[up][rr], lo, hi);
                int r = r0t + rr;
                float* dst = smem + (r >> 2) * PRIV + (r & 3);
                dst[n0 * 4]       = lo + bA;
                dst[(n0 + 1) * 4] = hi + bB;
            }
        }
    }
    __syncthreads();

    // ---- Phase 2: D sequential steps ----
    u64 S[8][4];
#pragma unroll
    for (int j = 0; j < 4; j++) {
        float4 b2v = *(const float4*)(g_b2r + j * 128 + lane * 4);
#pragma unroll
        for (int r = 0; r < 4; r++) {
            S[2 * j][r]     = pk2(b2v.x, b2v.y);
            S[2 * j + 1][r] = pk2(b2v.z, b2v.w);
        }
    }

    int kprev = 0;
    for (int i = 0; i < DN; i++) {
        const int ncur = cntd(i);

        // wait for this step's staged weights; barrier also orders last step's
        // rank-1 STS and protects the ring slot we are about to overwrite
        CP_WAIT0();
        __syncthreads();

        // prefetch next step's weight rows [cntd(i), cntd(i+1)) into other slot
        if (i < DN - 1) {
            const int k0 = ncur;
            const int nch = (cntd(i + 1) - k0) * (HN / 4);   // 16B chunks
            unsigned dst = smem_base + (WOFF + ((i + 1) & 1) * WSTRIDE) * 4;
            const float* src = g_W2r + k0 * HN;
            for (int c = t; c < nch; c += NTHR)
                cpa16(dst + c * 16, src + c * 4);
            CP_COMMIT();
        }

        // -- S update with newly frozen rows [kprev, ncur) from smem ring --
        {
            const float* wrow = smem + WOFF + (i & 1) * WSTRIDE + lane * 4;
#pragma unroll 1
            for (int k = kprev; k < ncur; k++) {
                const float* wp = wrow + (k - kprev) * HN;
                ulonglong2 q0 = *(const ulonglong2*)(wp);
                ulonglong2 q1 = *(const ulonglong2*)(wp + 128);
                ulonglong2 q2 = *(const ulonglong2*)(wp + 256);
                ulonglong2 q3 = *(const ulonglong2*)(wp + 384);
                float4 av = *(const float4*)(a1w + k * 4);   // relu'd, broadcast
                u64 h0 = dup2(av.x), h1 = dup2(av.y), h2 = dup2(av.z), h3 = dup2(av.w);
                fma2(S[0][0], q0.x, h0); fma2(S[0][1], q0.x, h1); fma2(S[0][2], q0.x, h2); fma2(S[0][3], q0.x, h3);
                fma2(S[1][0], q0.y, h0); fma2(S[1][1], q0.y, h1); fma2(S[1][2], q0.y, h2); fma2(S[1][3], q0.y, h3);
                fma2(S[2][0], q1.x, h0); fma2(S[2][1], q1.x, h1); fma2(S[2][2], q1.x, h2); fma2(S[2][3], q1.x, h3);
                fma2(S[3][0], q1.y, h0); fma2(S[3][1], q1.y, h1); fma2(S[3][2], q1.y, h2); fma2(S[3][3], q1.y, h3);
                fma2(S[4][0], q2.x, h0); fma2(S[4][1], q2.x, h1); fma2(S[4][2], q2.x, h2); fma2(S[4][3], q2.x, h3);
                fma2(S[5][0], q2.y, h0); fma2(S[5][1], q2.y, h1); fma2(S[5][2], q2.y, h2); fma2(S[5][3], q2.y, h3);
                fma2(S[6][0], q3.x, h0); fma2(S[6][1], q3.x, h1); fma2(S[6][2], q3.x, h2); fma2(S[6][3], q3.x, h3);
                fma2(S[7][0], q3.y, h0); fma2(S[7][1], q3.y, h1); fma2(S[7][2], q3.y, h2); fma2(S[7][3], q3.y, h3);
            }
        }
        kprev = ncur;

        // -- epilogue: P[r] += dup2(relu(S)) * (wm, ws), active quads only --
        u64 P[4] = {0ull, 0ull, 0ull, 0ull};
        const float* wpp = g_WomP + i * (2 * HN) + lane * 8;
#pragma unroll
        for (int j = 0; j < 4; j++) {
            if (j * 128 < ncur) {                    // warp-uniform quad skip
                ulonglong2 wa = *(const ulonglong2*)(wpp + j * 256);
                ulonglong2 wb = *(const ulonglong2*)(wpp + j * 256 + 4);
#pragma unroll
                for (int r = 0; r < 4; r++) {
                    float s0, s1, s2, s3;
                    unpk(S[2 * j][r], s0, s1);
                    unpk(S[2 * j + 1][r], s2, s3);
                    fma2(P[r], dup2(fmaxf(s0, 0.f)), wa.x);
                    fma2(P[r], dup2(fmaxf(s1, 0.f)), wa.y);
                    fma2(P[r], dup2(fmaxf(s2, 0.f)), wb.x);
                    fma2(P[r], dup2(fmaxf(s3, 0.f)), wb.y);
                }
            }
        }

        // u64 butterfly: all lanes end with full (mu, sc) per row
#pragma unroll
        for (int off = 16; off > 0; off >>= 1) {
#pragma unroll
            for (int r = 0; r < 4; r++) {
                u64 o = __shfl_xor_sync(0xffffffffu, P[r], off);
                add2(P[r], o);
            }
        }

        // -- z per row (redundant across lanes), fast softplus, direct store --
        float z[4];
        const float boi = __ldg(bo + i), bos = __ldg(bo + DN + i);
#pragma unroll
        for (int r = 0; r < 4; r++) {
            float muS, scS; unpk(P[r], muS, scS);
            float m  = muS + boi;
            float ps = scS + bos;
            float scl = fmaxf(ps, 0.f) + __logf(1.f + __expf(-fabsf(ps)));
            float ev  = smem[EPSOFF + i * EPSP + wid * 4 + r];
            float zz  = m + scl * ev;
            z[r] = zz;
            if (lane == r) {
                int g = (row0 + wid * 4 + r) * DN + i;
                out[g]               = zz;
                out[BN * DN + g]     = m;
                out[2 * BN * DN + g] = scl;
            }
        }

        // -- rank-1 a1 update on suffix [ncur, HN); freeze-relu [ncur, nfreeze) --
        if (i < DN - 1) {
            const int nfreeze = cntd(i + 1);
            const float* w1 = g_W1r + i * HN;
            for (int p = ncur + lane; p < HN; p += 32) {
                float w = w1[p];
                float4 a = *(float4*)(a1w + p * 4);
                a.x = fmaf(z[0], w, a.x);
                a.y = fmaf(z[1], w, a.y);
                a.z = fmaf(z[2], w, a.z);
                a.w = fmaf(z[3], w, a.w);
                if (p < nfreeze) {          // freezes now: apply relu permanently
                    a.x = fmaxf(a.x, 0.f);
                    a.y = fmaxf(a.y, 0.f);
                    a.z = fmaxf(a.z, 0.f);
                    a.w = fmaxf(a.w, 0.f);
                }
                *(float4*)(a1w + p * 4) = a;
            }
        }
    }
}

// ------------- launch ---------------------------------------------------------
extern "C" void kernel_launch(void* const* d_in, const int* in_sizes, int n_in,
                              void* d_out, int out_size) {
    (void)in_sizes; (void)n_in; (void)out_size;
    const float* ctx = (const float*)d_in[0];
    const float* eps = (const float*)d_in[1];
    const float* W1  = (const float*)d_in[2];
    const float* b1  = (const float*)d_in[3];
    const float* Wc  = (const float*)d_in[4];
    const float* W2  = (const float*)d_in[5];
    const float* b2  = (const float*)d_in[6];
    const float* Wo  = (const float*)d_in[7];
    const float* bo  = (const float*)d_in[8];
    float* out = (float*)d_out;

    prep_kernel<<<(HN * HN + 255) / 256, 256>>>(W1, b1, Wc, W2, b2, Wo);

    // smem: a1 8*2048 + weight ring 2*9*512 + eps 64*33 = 27712 floats = 110848 B
    const int smem_bytes = (8 * PRIV + 2 * WSTRIDE + DN * EPSP) * (int)sizeof(float);
    cudaFuncSetAttribute(made_kernel, cudaFuncAttributeMaxDynamicSharedMemorySize, smem_bytes);
    made_kernel<<<BN / ROWS, NTHR, smem_bytes>>>(ctx, eps, bo, out);
}